// round 9
// baseline (speedup 1.0000x reference)
#include <cuda_runtime.h>

#define Bn 2048
#define En 256
#define Hn 1024
#define Vn 42
#define XP 48      // x buffer padded width (zero padding cols 42..47)
#define Tn 100

// ---------------- persistent state (device globals; no allocation) ----------
__device__ float g_h0[2][Bn * Hn];
__device__ float g_h1[2][Bn * Hn];
__device__ float g_c0[Bn * Hn];
__device__ float g_c1[Bn * Hn];
__device__ float g_x[Bn * XP];

// ---------------- packed f32x2 helpers --------------------------------------
__device__ __forceinline__ unsigned long long pk2(float lo, float hi) {
    unsigned long long r;
    asm("mov.b64 %0, {%1, %2};" : "=l"(r) : "f"(lo), "f"(hi));
    return r;
}
__device__ __forceinline__ void fma2(unsigned long long& d, unsigned long long a,
                                     unsigned long long b) {
    asm("fma.rn.f32x2 %0, %1, %2, %0;" : "+l"(d) : "l"(a), "l"(b));
}
__device__ __forceinline__ float2 unpk2(unsigned long long v) {
    float2 r;
    asm("mov.b64 {%0, %1}, %2;" : "=f"(r.x), "=f"(r.y) : "l"(v));
    return r;
}
__device__ __forceinline__ float sigf(float x) { return 1.0f / (1.0f + expf(-x)); }

// ---------------- init: zero states, one-hot start token --------------------
__global__ void init_kernel() {
    int idx = blockIdx.x * blockDim.x + threadIdx.x;   // grid covers Bn*Hn exactly
    g_h1[0][idx] = 0.0f;
    g_c0[idx]    = 0.0f;
    g_c1[idx]    = 0.0f;
    if (idx < Bn * XP) {
        g_x[idx] = ((idx % XP) == (Vn - 1)) ? 1.0f : 0.0f;
    }
}

// ---------------- fc1: h0 = latent @ fc1_w^T + fc1_b ------------------------
// BM=64, BN=64, BK=16, 256 threads, TM=4, TN=4
__global__ __launch_bounds__(256) void fc1_kernel(const float* __restrict__ A,
                                                  const float* __restrict__ W,
                                                  const float* __restrict__ bias) {
    __shared__ __align__(16) float As[16][64];
    __shared__ __align__(16) float Bs[16][64];
    const int tid = threadIdx.x;
    const int tx = tid & 15, ty = tid >> 4;
    const int m0 = blockIdx.y * 64;
    const int n0 = blockIdx.x * 64;

    float acc[4][4];
#pragma unroll
    for (int i = 0; i < 4; i++)
#pragma unroll
        for (int j = 0; j < 4; j++) acc[i][j] = 0.0f;

    const int rA = tid >> 2;          // 0..63
    const int qA = (tid & 3) * 4;     // 0,4,8,12

    for (int k0 = 0; k0 < En; k0 += 16) {
        float4 av = *(const float4*)(A + (m0 + rA) * En + k0 + qA);
        As[qA + 0][rA] = av.x; As[qA + 1][rA] = av.y;
        As[qA + 2][rA] = av.z; As[qA + 3][rA] = av.w;
        float4 wv = *(const float4*)(W + (n0 + rA) * En + k0 + qA);
        Bs[qA + 0][rA] = wv.x; Bs[qA + 1][rA] = wv.y;
        Bs[qA + 2][rA] = wv.z; Bs[qA + 3][rA] = wv.w;
        __syncthreads();
#pragma unroll
        for (int k = 0; k < 16; k++) {
            float4 a4 = *(const float4*)&As[k][ty * 4];
            float4 b4 = *(const float4*)&Bs[k][tx * 4];
            float aa[4] = {a4.x, a4.y, a4.z, a4.w};
            float bb[4] = {b4.x, b4.y, b4.z, b4.w};
#pragma unroll
            for (int i = 0; i < 4; i++)
#pragma unroll
                for (int j = 0; j < 4; j++) acc[i][j] += aa[i] * bb[j];
        }
        __syncthreads();
    }
#pragma unroll
    for (int i = 0; i < 4; i++) {
        int m = m0 + ty * 4 + i;
#pragma unroll
        for (int j = 0; j < 4; j++) {
            int n = n0 + tx * 4 + j;
            g_h0[0][m * Hn + n] = acc[i][j] + bias[n];
        }
    }
}

// ---------------- fused gate GEMM + LSTM cell -------------------------------
// BM=128 rows, BN=32 hidden units (=> 128 gate columns), 256 threads.
// Each thread: 8 rows x 2 adjacent hidden cols x 4 gates, f32x2-packed accums.
__global__ __launch_bounds__(256, 2) void gate_kernel(
    int layer, int cur,
    const float* __restrict__ w_ih, const float* __restrict__ w_hh,
    const float* __restrict__ b_ih, const float* __restrict__ b_hh) {
    __shared__ __align__(16) float As[16][128];
    __shared__ __align__(16) float Ws[4][16][32];

    const int tid = threadIdx.x;
    const int tx = tid & 15, ty = tid >> 4;
    const int m0 = blockIdx.y * 128;
    const int n0 = blockIdx.x * 32;
    const int nxt = cur ^ 1;

    const float* A1;
    const float* A2;
    float* cst;
    float* hout;
    int lda1, kp1, kr1, ldw1;
    if (layer == 0) {
        A1 = g_x; lda1 = XP; kp1 = XP; kr1 = Vn; ldw1 = Vn;
        A2 = g_h0[cur]; cst = g_c0; hout = g_h0[nxt];
    } else {
        A1 = g_h0[nxt]; lda1 = Hn; kp1 = Hn; kr1 = Hn; ldw1 = Hn;
        A2 = g_h1[cur]; cst = g_c1; hout = g_h1[nxt];
    }

    unsigned long long acc[4][8];
#pragma unroll
    for (int g = 0; g < 4; g++)
#pragma unroll
        for (int i = 0; i < 8; i++) acc[g][i] = 0ULL;

    const int mA = tid >> 2;          // 0..63
    const int qA = (tid & 3) * 4;     // 0,4,8,12
    const int pW = tid & 15;          // n-pair index
    const int kW = (tid >> 4) & 15;   // k within chunk

#pragma unroll 1
    for (int src = 0; src < 2; src++) {
        const float* A = src ? A2 : A1;
        const float* W = src ? w_hh : w_ih;
        const int lda = src ? Hn : lda1;
        const int ldw = src ? Hn : ldw1;
        const int kp  = src ? Hn : kp1;
        const int kr  = src ? Hn : kr1;

        for (int k0 = 0; k0 < kp; k0 += 16) {
            // A tile: [16 k][128 m], two coalesced float4 per thread
            float4 a0 = *(const float4*)(A + (m0 + mA) * lda + k0 + qA);
            float4 a1 = *(const float4*)(A + (m0 + mA + 64) * lda + k0 + qA);
            As[qA + 0][mA] = a0.x; As[qA + 1][mA] = a0.y;
            As[qA + 2][mA] = a0.z; As[qA + 3][mA] = a0.w;
            As[qA + 0][mA + 64] = a1.x; As[qA + 1][mA + 64] = a1.y;
            As[qA + 2][mA + 64] = a1.z; As[qA + 3][mA + 64] = a1.w;
            // W tiles, one per gate: guarded scalar loads, paired STS.64
            const int kk = k0 + kW;
            const bool ok = kk < kr;
#pragma unroll
            for (int g = 0; g < 4; g++) {
                const float* wr = W + (size_t)(g * Hn + n0 + 2 * pW) * ldw + kk;
                float w0 = ok ? wr[0] : 0.0f;
                float w1 = ok ? wr[ldw] : 0.0f;
                *(float2*)&Ws[g][kW][2 * pW] = make_float2(w0, w1);
            }
            __syncthreads();
#pragma unroll
            for (int k = 0; k < 16; k++) {
                float4 aA = *(const float4*)&As[k][ty * 8];
                float4 aB = *(const float4*)&As[k][ty * 8 + 4];
                unsigned long long wv[4];
#pragma unroll
                for (int g = 0; g < 4; g++)
                    wv[g] = *(const unsigned long long*)&Ws[g][k][tx * 2];
                unsigned long long pa[8];
                pa[0] = pk2(aA.x, aA.x); pa[1] = pk2(aA.y, aA.y);
                pa[2] = pk2(aA.z, aA.z); pa[3] = pk2(aA.w, aA.w);
                pa[4] = pk2(aB.x, aB.x); pa[5] = pk2(aB.y, aB.y);
                pa[6] = pk2(aB.z, aB.z); pa[7] = pk2(aB.w, aB.w);
#pragma unroll
                for (int g = 0; g < 4; g++)
#pragma unroll
                    for (int i = 0; i < 8; i++) fma2(acc[g][i], pa[i], wv[g]);
            }
            __syncthreads();
        }
    }

    // ---- fused LSTM cell epilogue (gate order i, f, g, o) ----
    const int nb = n0 + tx * 2;
    float bsum[4][2];
#pragma unroll
    for (int g = 0; g < 4; g++) {
        bsum[g][0] = b_ih[g * Hn + nb] + b_hh[g * Hn + nb];
        bsum[g][1] = b_ih[g * Hn + nb + 1] + b_hh[g * Hn + nb + 1];
    }
#pragma unroll
    for (int i = 0; i < 8; i++) {
        const int m = m0 + ty * 8 + i;
        float2 vi = unpk2(acc[0][i]);
        float2 vf = unpk2(acc[1][i]);
        float2 vg = unpk2(acc[2][i]);
        float2 vo = unpk2(acc[3][i]);
        {
            int idx = m * Hn + nb;
            float ii = sigf(vi.x + bsum[0][0]);
            float ff = sigf(vf.x + bsum[1][0]);
            float gg = tanhf(vg.x + bsum[2][0]);
            float oo = sigf(vo.x + bsum[3][0]);
            float cn = ff * cst[idx] + ii * gg;
            cst[idx] = cn;
            hout[idx] = oo * tanhf(cn);
        }
        {
            int idx = m * Hn + nb + 1;
            float ii = sigf(vi.y + bsum[0][1]);
            float ff = sigf(vf.y + bsum[1][1]);
            float gg = tanhf(vg.y + bsum[2][1]);
            float oo = sigf(vo.y + bsum[3][1]);
            float cn = ff * cst[idx] + ii * gg;
            cst[idx] = cn;
            hout[idx] = oo * tanhf(cn);
        }
    }
}

// ---------------- logits GEMM + softmax feedback ----------------------------
// 512 threads = 16 warps, one row per warp, 128 CTAs.
__global__ __launch_bounds__(512) void logits_kernel(int hbuf,
                                                     const float* __restrict__ fc2_w,
                                                     const float* __restrict__ fc2_b,
                                                     float* __restrict__ out, int t) {
    __shared__ float ws[Vn * 128];
    __shared__ float bs[Vn];
    __shared__ float part[16][Vn];

    const int tid = threadIdx.x;
    const int warp = tid >> 5, lane = tid & 31;
    const int row = blockIdx.x * 16 + warp;
    const float* h1 = g_h1[hbuf] + row * Hn;

    if (tid < Vn) bs[tid] = fc2_b[tid];

    float acc[Vn];
#pragma unroll
    for (int v = 0; v < Vn; v++) acc[v] = 0.0f;

    for (int kc = 0; kc < Hn; kc += 128) {
        __syncthreads();
        for (int idx = tid; idx < Vn * 128; idx += 512) {
            int v = idx >> 7, k = idx & 127;
            ws[idx] = fc2_w[v * Hn + kc + k];
        }
        __syncthreads();
        float hv[4];
#pragma unroll
        for (int j = 0; j < 4; j++) hv[j] = h1[kc + j * 32 + lane];
#pragma unroll
        for (int v = 0; v < Vn; v++) {
#pragma unroll
            for (int j = 0; j < 4; j++) acc[v] += ws[v * 128 + j * 32 + lane] * hv[j];
        }
    }
    // per-warp reduction of 42 dot products
#pragma unroll
    for (int v = 0; v < Vn; v++) {
        float s = acc[v];
        s += __shfl_down_sync(0xFFFFFFFFu, s, 16);
        s += __shfl_down_sync(0xFFFFFFFFu, s, 8);
        s += __shfl_down_sync(0xFFFFFFFFu, s, 4);
        s += __shfl_down_sync(0xFFFFFFFFu, s, 2);
        s += __shfl_down_sync(0xFFFFFFFFu, s, 1);
        if (lane == 0) part[warp][v] = s;
    }
    __syncwarp();

    // lanes 0..31 own col=lane; lanes 0..9 also own col=32+lane
    float p0 = part[warp][lane] + bs[lane];
    bool has1 = lane < (Vn - 32);
    float p1 = has1 ? (part[warp][32 + lane] + bs[32 + lane]) : -1e30f;

    // write logits (pre-softmax)
    out[row * (Tn * Vn) + t * Vn + lane] = p0;
    if (has1) out[row * (Tn * Vn) + t * Vn + 32 + lane] = p1;

    // softmax -> next-step input x
    float mx = fmaxf(p0, p1);
#pragma unroll
    for (int o = 16; o > 0; o >>= 1) mx = fmaxf(mx, __shfl_xor_sync(0xFFFFFFFFu, mx, o));
    float e0 = expf(p0 - mx);
    float e1 = has1 ? expf(p1 - mx) : 0.0f;
    float sm = e0 + e1;
#pragma unroll
    for (int o = 16; o > 0; o >>= 1) sm += __shfl_xor_sync(0xFFFFFFFFu, sm, o);
    float inv = 1.0f / sm;
    g_x[row * XP + lane] = e0 * inv;
    if (has1) g_x[row * XP + 32 + lane] = e1 * inv;
}

// ---------------- driver ----------------------------------------------------
extern "C" void kernel_launch(void* const* d_in, const int* in_sizes, int n_in,
                              void* d_out, int out_size) {
    (void)in_sizes; (void)n_in; (void)out_size;
    const float* latent = (const float*)d_in[0];
    const float* fc1_w  = (const float*)d_in[1];
    const float* fc1_b  = (const float*)d_in[2];
    const float* fc2_w  = (const float*)d_in[3];
    const float* fc2_b  = (const float*)d_in[4];
    const float* w_ih0  = (const float*)d_in[5];
    const float* w_hh0  = (const float*)d_in[6];
    const float* b_ih0  = (const float*)d_in[7];
    const float* b_hh0  = (const float*)d_in[8];
    const float* w_ih1  = (const float*)d_in[9];
    const float* w_hh1  = (const float*)d_in[10];
    const float* b_ih1  = (const float*)d_in[11];
    const float* b_hh1  = (const float*)d_in[12];
    float* out = (float*)d_out;

    // init states (covers Bn*Hn = 2M elements exactly)
    init_kernel<<<(Bn * Hn) / 512, 512>>>();
    // h0 = fc1(latent)
    {
        dim3 grid(Hn / 64, Bn / 64);
        fc1_kernel<<<grid, 256>>>(latent, fc1_w, fc1_b);
    }

    dim3 ggrid(Hn / 32, Bn / 128);
    int cur = 0;
    for (int t = 0; t < Tn; t++) {
        gate_kernel<<<ggrid, 256>>>(0, cur, w_ih0, w_hh0, b_ih0, b_hh0);
        gate_kernel<<<ggrid, 256>>>(1, cur, w_ih1, w_hh1, b_ih1, b_hh1);
        logits_kernel<<<Bn / 16, 512>>>(cur ^ 1, fc2_w, fc2_b, out, t);
        cur ^= 1;
    }
}

// round 15
// speedup vs baseline: 1.5043x; 1.5043x over previous
#include <cuda_runtime.h>
#include <cstdint>

#define Bn 2048
#define En 256
#define Hn 1024
#define Vn 42
#define KX 48        // padded x width (rows 42..47 zero)
#define Tn 100
#define NCH_X (KX / 16)   // 3 chunks for x segment
#define NCH_H (Hn / 16)   // 64 chunks for h segment

// ---------------- persistent state (device globals; no allocation) ----------
// Transposed activations [k][m] for cp.async-friendly A tiles.
__device__ float g_h0T[2][Hn * Bn];
__device__ float g_h1T[2][Hn * Bn];
__device__ float g_h1R[2][Bn * Hn];   // row-major h1 for logits kernel
__device__ float g_c0[Bn * Hn];
__device__ float g_c1[Bn * Hn];
__device__ float g_xT[KX * Bn];

// Packed weights: [nt(32)][chunk][g(4)][k(16)][n(32)] -> 2048 floats per tile,
// exactly the smem Ws layout, zero-padded past Ksrc.
__device__ float g_Wih0[(size_t)32 * NCH_X * 2048];
__device__ float g_Whh0[(size_t)32 * NCH_H * 2048];
__device__ float g_Wih1[(size_t)32 * NCH_H * 2048];
__device__ float g_Whh1[(size_t)32 * NCH_H * 2048];

// ---------------- packed f32x2 helpers --------------------------------------
__device__ __forceinline__ unsigned long long pk2(float lo, float hi) {
    unsigned long long r;
    asm("mov.b64 %0, {%1, %2};" : "=l"(r) : "f"(lo), "f"(hi));
    return r;
}
__device__ __forceinline__ void fma2(unsigned long long& d, unsigned long long a,
                                     unsigned long long b) {
    asm("fma.rn.f32x2 %0, %1, %2, %0;" : "+l"(d) : "l"(a), "l"(b));
}
__device__ __forceinline__ float2 unpk2(unsigned long long v) {
    float2 r;
    asm("mov.b64 {%0, %1}, %2;" : "=f"(r.x), "=f"(r.y) : "l"(v));
    return r;
}
__device__ __forceinline__ float sigf(float x) { return 1.0f / (1.0f + expf(-x)); }

// ---------------- cp.async helpers ------------------------------------------
__device__ __forceinline__ void cpa16(uint32_t dst, const float* src) {
    asm volatile("cp.async.cg.shared.global [%0], [%1], 16;\n" :: "r"(dst), "l"(src));
}
__device__ __forceinline__ void cpa_commit() {
    asm volatile("cp.async.commit_group;\n");
}
__device__ __forceinline__ void cpa_wait1() {
    asm volatile("cp.async.wait_group 1;\n");
}
__device__ __forceinline__ void cpa_wait0() {
    asm volatile("cp.async.wait_group 0;\n");
}

// ---------------- weight pack kernel ----------------------------------------
// grid = 32*nch*4 blocks (nt, ch, g), block = 512 (k=tid>>5, n=tid&31)
__global__ void pack_kernel(const float* __restrict__ W, float* __restrict__ Wp,
                            int ldw, int Ksrc, int nch) {
    int bx = blockIdx.x;
    int g  = bx & 3;
    int ch = (bx >> 2) % nch;
    int nt = bx / (4 * nch);
    int tid = threadIdx.x;
    int k = tid >> 5, n = tid & 31;
    int ksrc = ch * 16 + k;
    float v = (ksrc < Ksrc) ? W[(size_t)(g * Hn + nt * 32 + n) * ldw + ksrc] : 0.0f;
    Wp[(size_t)(nt * nch + ch) * 2048 + g * 512 + k * 32 + n] = v;
}

// ---------------- init: zero states, one-hot start token (transposed) -------
__global__ void init_kernel() {
    int idx = blockIdx.x * blockDim.x + threadIdx.x;   // covers Bn*Hn
    g_h1T[0][idx] = 0.0f;
    g_c0[idx]     = 0.0f;
    g_c1[idx]     = 0.0f;
    if (idx < KX * Bn) {
        g_xT[idx] = ((idx / Bn) == (Vn - 1)) ? 1.0f : 0.0f;
    }
}

// ---------------- fc1: h0T = (latent @ fc1_w^T + fc1_b)^T -------------------
__global__ __launch_bounds__(256) void fc1_kernel(const float* __restrict__ A,
                                                  const float* __restrict__ W,
                                                  const float* __restrict__ bias) {
    __shared__ __align__(16) float As[16][64];
    __shared__ __align__(16) float Bs[16][64];
    const int tid = threadIdx.x;
    const int tx = tid & 15, ty = tid >> 4;
    const int m0 = blockIdx.y * 64;
    const int n0 = blockIdx.x * 64;

    float acc[4][4];
#pragma unroll
    for (int i = 0; i < 4; i++)
#pragma unroll
        for (int j = 0; j < 4; j++) acc[i][j] = 0.0f;

    const int rA = tid >> 2;
    const int qA = (tid & 3) * 4;

    for (int k0 = 0; k0 < En; k0 += 16) {
        float4 av = *(const float4*)(A + (m0 + rA) * En + k0 + qA);
        As[qA + 0][rA] = av.x; As[qA + 1][rA] = av.y;
        As[qA + 2][rA] = av.z; As[qA + 3][rA] = av.w;
        float4 wv = *(const float4*)(W + (n0 + rA) * En + k0 + qA);
        Bs[qA + 0][rA] = wv.x; Bs[qA + 1][rA] = wv.y;
        Bs[qA + 2][rA] = wv.z; Bs[qA + 3][rA] = wv.w;
        __syncthreads();
#pragma unroll
        for (int k = 0; k < 16; k++) {
            float4 a4 = *(const float4*)&As[k][ty * 4];
            float4 b4 = *(const float4*)&Bs[k][tx * 4];
            float aa[4] = {a4.x, a4.y, a4.z, a4.w};
            float bb[4] = {b4.x, b4.y, b4.z, b4.w};
#pragma unroll
            for (int i = 0; i < 4; i++)
#pragma unroll
                for (int j = 0; j < 4; j++) acc[i][j] += aa[i] * bb[j];
        }
        __syncthreads();
    }
#pragma unroll
    for (int i = 0; i < 4; i++) {
        int m = m0 + ty * 4 + i;
#pragma unroll
        for (int j = 0; j < 4; j++) {
            int n = n0 + tx * 4 + j;
            g_h0T[0][(size_t)n * Bn + m] = acc[i][j] + bias[n];   // transposed store
        }
    }
}

// ---------------- fused gate GEMM + LSTM cell (cp.async pipelined) -----------
// BM=128 rows, BN=32 hidden units (128 gate cols), 256 threads.
__global__ __launch_bounds__(256, 2) void gate_kernel(
    int layer, int cur,
    const float* __restrict__ b_ih, const float* __restrict__ b_hh) {
    __shared__ __align__(16) float As[2][16][128];
    __shared__ __align__(16) float Ws[2][2048];   // [g(4)][k(16)][n(32)]

    const int tid = threadIdx.x;
    const int tx = tid & 15, ty = tid >> 4;
    const int bxn = blockIdx.x;            // n-tile 0..31
    const int m0 = blockIdx.y * 128;
    const int n0 = bxn * 32;
    const int nxt = cur ^ 1;

    const float* Aseg[2];
    const float* Wseg[2];
    int nch0, nch1;
    float* cst;
    float* houtT;
    float* houtR;
    if (layer == 0) {
        Aseg[0] = g_xT;        Wseg[0] = g_Wih0; nch0 = NCH_X;
        Aseg[1] = g_h0T[cur];  Wseg[1] = g_Whh0; nch1 = NCH_H;
        cst = g_c0; houtT = g_h0T[nxt]; houtR = nullptr;
    } else {
        Aseg[0] = g_h0T[nxt];  Wseg[0] = g_Wih1; nch0 = NCH_H;
        Aseg[1] = g_h1T[cur];  Wseg[1] = g_Whh1; nch1 = NCH_H;
        cst = g_c1; houtT = g_h1T[nxt]; houtR = g_h1R[nxt];
    }
    const int total = nch0 + nch1;

    const uint32_t sAs = (uint32_t)__cvta_generic_to_shared(&As[0][0][0]);
    const uint32_t sWs = (uint32_t)__cvta_generic_to_shared(&Ws[0][0]);

    unsigned long long acc[4][8];
#pragma unroll
    for (int g = 0; g < 4; g++)
#pragma unroll
        for (int i = 0; i < 8; i++) acc[g][i] = 0ULL;

    // ---- chunk issue: A tile (16 rows x 512B) + W tile (8KB contiguous) ----
    auto issue = [&](int gch, int buf) {
        int seg = (gch >= nch0) ? 1 : 0;
        int ch = seg ? (gch - nch0) : gch;
        int nch = seg ? nch1 : nch0;
        const float* A = Aseg[seg];
        const float* W = Wseg[seg] + (size_t)(bxn * nch + ch) * 2048;
#pragma unroll
        for (int r = 0; r < 2; r++) {
            int gI = tid + r * 256;               // 0..511
            int row = gI >> 5, c4 = (gI & 31) * 4;
            cpa16(sAs + (uint32_t)(((buf * 16 + row) * 128 + c4) * 4),
                  A + (size_t)(ch * 16 + row) * Bn + m0 + c4);
            cpa16(sWs + (uint32_t)((buf * 2048 + gI * 4) * 4),
                  W + gI * 4);
        }
        cpa_commit();
    };

    issue(0, 0);
    for (int gch = 0; gch < total; gch++) {
        const int buf = gch & 1;
        if (gch + 1 < total) {
            issue(gch + 1, (gch + 1) & 1);
            cpa_wait1();
        } else {
            cpa_wait0();
        }
        __syncthreads();
        const float(*Wb)[16][32] = (const float(*)[16][32])&Ws[buf][0];
#pragma unroll
        for (int k = 0; k < 16; k++) {
            float4 aA = *(const float4*)&As[buf][k][ty * 8];
            float4 aB = *(const float4*)&As[buf][k][ty * 8 + 4];
            unsigned long long wv[4];
#pragma unroll
            for (int g = 0; g < 4; g++)
                wv[g] = *(const unsigned long long*)&Wb[g][k][tx * 2];
            unsigned long long pa[8];
            pa[0] = pk2(aA.x, aA.x); pa[1] = pk2(aA.y, aA.y);
            pa[2] = pk2(aA.z, aA.z); pa[3] = pk2(aA.w, aA.w);
            pa[4] = pk2(aB.x, aB.x); pa[5] = pk2(aB.y, aB.y);
            pa[6] = pk2(aB.z, aB.z); pa[7] = pk2(aB.w, aB.w);
#pragma unroll
            for (int g = 0; g < 4; g++)
#pragma unroll
                for (int i = 0; i < 8; i++) fma2(acc[g][i], pa[i], wv[g]);
        }
        __syncthreads();
    }

    // ---- fused LSTM cell epilogue (gate order i, f, g, o) ----
    const int nb = n0 + tx * 2;
    float bsum[4][2];
#pragma unroll
    for (int g = 0; g < 4; g++) {
        bsum[g][0] = b_ih[g * Hn + nb] + b_hh[g * Hn + nb];
        bsum[g][1] = b_ih[g * Hn + nb + 1] + b_hh[g * Hn + nb + 1];
    }
#pragma unroll
    for (int i = 0; i < 8; i++) {
        const int m = m0 + ty * 8 + i;
        float2 vi = unpk2(acc[0][i]);
        float2 vf = unpk2(acc[1][i]);
        float2 vg = unpk2(acc[2][i]);
        float2 vo = unpk2(acc[3][i]);
        {
            int idx = m * Hn + nb;
            float ii = sigf(vi.x + bsum[0][0]);
            float ff = sigf(vf.x + bsum[1][0]);
            float gg = tanhf(vg.x + bsum[2][0]);
            float oo = sigf(vo.x + bsum[3][0]);
            float cn = ff * cst[idx] + ii * gg;
            cst[idx] = cn;
            float hv = oo * tanhf(cn);
            houtT[(size_t)nb * Bn + m] = hv;
            if (houtR) houtR[idx] = hv;
        }
        {
            int idx = m * Hn + nb + 1;
            float ii = sigf(vi.y + bsum[0][1]);
            float ff = sigf(vf.y + bsum[1][1]);
            float gg = tanhf(vg.y + bsum[2][1]);
            float oo = sigf(vo.y + bsum[3][1]);
            float cn = ff * cst[idx] + ii * gg;
            cst[idx] = cn;
            float hv = oo * tanhf(cn);
            houtT[(size_t)(nb + 1) * Bn + m] = hv;
            if (houtR) houtR[idx] = hv;
        }
    }
}

// ---------------- logits GEMM + softmax feedback ----------------------------
__global__ __launch_bounds__(512) void logits_kernel(int hbuf,
                                                     const float* __restrict__ fc2_w,
                                                     const float* __restrict__ fc2_b,
                                                     float* __restrict__ out, int t) {
    __shared__ float ws[Vn * 128];
    __shared__ float bs[Vn];
    __shared__ float part[16][Vn];

    const int tid = threadIdx.x;
    const int warp = tid >> 5, lane = tid & 31;
    const int row = blockIdx.x * 16 + warp;
    const float* h1 = g_h1R[hbuf] + (size_t)row * Hn;

    if (tid < Vn) bs[tid] = fc2_b[tid];

    float acc[Vn];
#pragma unroll
    for (int v = 0; v < Vn; v++) acc[v] = 0.0f;

    for (int kc = 0; kc < Hn; kc += 128) {
        __syncthreads();
        for (int idx = tid; idx < Vn * 128; idx += 512) {
            int v = idx >> 7, k = idx & 127;
            ws[idx] = fc2_w[v * Hn + kc + k];
        }
        __syncthreads();
        float hv[4];
#pragma unroll
        for (int j = 0; j < 4; j++) hv[j] = h1[kc + j * 32 + lane];
#pragma unroll
        for (int v = 0; v < Vn; v++) {
#pragma unroll
            for (int j = 0; j < 4; j++) acc[v] += ws[v * 128 + j * 32 + lane] * hv[j];
        }
    }
#pragma unroll
    for (int v = 0; v < Vn; v++) {
        float s = acc[v];
        s += __shfl_down_sync(0xFFFFFFFFu, s, 16);
        s += __shfl_down_sync(0xFFFFFFFFu, s, 8);
        s += __shfl_down_sync(0xFFFFFFFFu, s, 4);
        s += __shfl_down_sync(0xFFFFFFFFu, s, 2);
        s += __shfl_down_sync(0xFFFFFFFFu, s, 1);
        if (lane == 0) part[warp][v] = s;
    }
    __syncwarp();

    float p0 = part[warp][lane] + bs[lane];
    bool has1 = lane < (Vn - 32);
    float p1 = has1 ? (part[warp][32 + lane] + bs[32 + lane]) : -1e30f;

    out[(size_t)row * (Tn * Vn) + t * Vn + lane] = p0;
    if (has1) out[(size_t)row * (Tn * Vn) + t * Vn + 32 + lane] = p1;

    float mx = fmaxf(p0, p1);
#pragma unroll
    for (int o = 16; o > 0; o >>= 1) mx = fmaxf(mx, __shfl_xor_sync(0xFFFFFFFFu, mx, o));
    float e0 = expf(p0 - mx);
    float e1 = has1 ? expf(p1 - mx) : 0.0f;
    float sm = e0 + e1;
#pragma unroll
    for (int o = 16; o > 0; o >>= 1) sm += __shfl_xor_sync(0xFFFFFFFFu, sm, o);
    float inv = 1.0f / sm;
    g_xT[(size_t)lane * Bn + row] = e0 * inv;                     // transposed x
    if (has1) g_xT[(size_t)(32 + lane) * Bn + row] = e1 * inv;
}

// ---------------- driver ----------------------------------------------------
extern "C" void kernel_launch(void* const* d_in, const int* in_sizes, int n_in,
                              void* d_out, int out_size) {
    (void)in_sizes; (void)n_in; (void)out_size;
    const float* latent = (const float*)d_in[0];
    const float* fc1_w  = (const float*)d_in[1];
    const float* fc1_b  = (const float*)d_in[2];
    const float* fc2_w  = (const float*)d_in[3];
    const float* fc2_b  = (const float*)d_in[4];
    const float* w_ih0  = (const float*)d_in[5];
    const float* w_hh0  = (const float*)d_in[6];
    const float* b_ih0  = (const float*)d_in[7];
    const float* b_hh0  = (const float*)d_in[8];
    const float* w_ih1  = (const float*)d_in[9];
    const float* w_hh1  = (const float*)d_in[10];
    const float* b_ih1  = (const float*)d_in[11];
    const float* b_hh1  = (const float*)d_in[12];
    float* out = (float*)d_out;

    float* p_Wih0; cudaGetSymbolAddress((void**)&p_Wih0, g_Wih0);
    float* p_Whh0; cudaGetSymbolAddress((void**)&p_Whh0, g_Whh0);
    float* p_Wih1; cudaGetSymbolAddress((void**)&p_Wih1, g_Wih1);
    float* p_Whh1; cudaGetSymbolAddress((void**)&p_Whh1, g_Whh1);

    // pack weights (constant per launch; graph-replayed deterministically)
    pack_kernel<<<32 * NCH_X * 4, 512>>>(w_ih0, p_Wih0, Vn, Vn, NCH_X);
    pack_kernel<<<32 * NCH_H * 4, 512>>>(w_hh0, p_Whh0, Hn, Hn, NCH_H);
    pack_kernel<<<32 * NCH_H * 4, 512>>>(w_ih1, p_Wih1, Hn, Hn, NCH_H);
    pack_kernel<<<32 * NCH_H * 4, 512>>>(w_hh1, p_Whh1, Hn, Hn, NCH_H);

    init_kernel<<<(Bn * Hn) / 512, 512>>>();
    {
        dim3 grid(Hn / 64, Bn / 64);
        fc1_kernel<<<grid, 256>>>(latent, fc1_w, fc1_b);
    }

    dim3 ggrid(Hn / 32, Bn / 128);
    int cur = 0;
    for (int t = 0; t < Tn; t++) {
        gate_kernel<<<ggrid, 256>>>(0, cur, b_ih0, b_hh0);
        gate_kernel<<<ggrid, 256>>>(1, cur, b_ih1, b_hh1);
        logits_kernel<<<Bn / 16, 512>>>(cur ^ 1, fc2_w, fc2_b, out, t);
        cur ^= 1;
    }
}